// round 14
// baseline (speedup 1.0000x reference)
#include <cuda_runtime.h>
#include <cstdint>

// Problem constants (fixed by reference setup_inputs)
#define BATCH 128
#define SEQ   8192
#define FEAT  32
#define EVAL_POS 4096
#define TRAIN_ELEMS (EVAL_POS * FEAT)    // 131072 per batch
#define BATCH_ELEMS (SEQ * FEAT)         // 262144 per batch
#define TRAIN_VEC4  (TRAIN_ELEMS / 4)    // 32768 float4 per batch
#define BATCH_VEC4  (BATCH_ELEMS / 4)    // 65536 float4 per batch

#define FULL_MASK 0xFFFFu                // all 16 classes present

// MLP=1 extrapolation of the measured trend: steady-state dur improves as
// front-batched loads per warp (MLP_p1) decrease (MLP4 variants: 45.06us;
// MLP2 after-barrier: 43.68/43.87us). This round: 1 float4 per thread.
//   - 256 blocks per batch, 256 threads, 1 float4 per thread
//     (256 * 256 = 65536 = BATCH_VEC4)
//   - warp 0 computes the batch presence mask with early exit (monotone OR:
//     exiting when saturated is always safe; ~2 L2-hit iterations on this
//     data, all blocks of a batch read the same prefix bytes).
//   - rank(v) = popc(mask & ((1<<v)-1)); __ldcs/__stcs streaming hints.
__global__ __launch_bounds__(256)
void fused_rank_kernel(const float4* __restrict__ x, float4* __restrict__ out)
{
    const int b = blockIdx.x >> 8;                 // 256 blocks per batch
    const size_t base = (size_t)b * BATCH_VEC4;

    __shared__ unsigned int s_mask;

    if (threadIdx.x < 32) {
        const float4* __restrict__ p = x + base;
        unsigned int m = 0;
        for (int i = threadIdx.x; i < TRAIN_VEC4; i += 32) {
            float4 v = __ldg(&p[i]);
            m |= 1u << (int)v.x;
            m |= 1u << (int)v.y;
            m |= 1u << (int)v.z;
            m |= 1u << (int)v.w;
            // warp-union early exit (safe: OR is monotone)
            if (__reduce_or_sync(0xffffffffu, m) == FULL_MASK) { m = FULL_MASK; break; }
        }
        m = __reduce_or_sync(0xffffffffu, m);
        if (threadIdx.x == 0) s_mask = m;
    }
    __syncthreads();
    const unsigned int mask = s_mask;

    // Rank phase: 256 float4 per block, 1 per thread.
    const size_t i0 = base + ((size_t)(blockIdx.x & 255) << 8) + threadIdx.x;

    float4 v0 = __ldcs(&x[i0]);

    float4 r0;
    r0.x = (float)__popc(mask & ((1u << (int)v0.x) - 1u));
    r0.y = (float)__popc(mask & ((1u << (int)v0.y) - 1u));
    r0.z = (float)__popc(mask & ((1u << (int)v0.z) - 1u));
    r0.w = (float)__popc(mask & ((1u << (int)v0.w) - 1u));

    __stcs(&out[i0], r0);
}

extern "C" void kernel_launch(void* const* d_in, const int* in_sizes, int n_in,
                              void* d_out, int out_size)
{
    const float4* x  = (const float4*)d_in[0];   // [B, S, F] float32
    float4* out      = (float4*)d_out;           // [B, S, F] float32

    const int blocks = BATCH * 256;              // 32768
    fused_rank_kernel<<<blocks, 256>>>(x, out);
}

// round 15
// speedup vs baseline: 1.1154x; 1.1154x over previous
#include <cuda_runtime.h>
#include <cstdint>

// Problem constants (fixed by reference setup_inputs)
#define BATCH 128
#define SEQ   8192
#define FEAT  32
#define EVAL_POS 4096
#define TRAIN_ELEMS (EVAL_POS * FEAT)    // 131072 per batch
#define BATCH_ELEMS (SEQ * FEAT)         // 262144 per batch
#define TRAIN_VEC4  (TRAIN_ELEMS / 4)    // 32768 float4 per batch
#define BATCH_VEC4  (BATCH_ELEMS / 4)    // 65536 float4 per batch

#define FULL_MASK 0xFFFFu                // all 16 classes present

// Barrier-free variant of the best kernel (R3 shape: 128 blocks/batch,
// 2 float4/thread):
//   - EVERY warp computes the batch presence mask independently with the
//     monotone-OR early exit. All warps read the IDENTICAL prefix
//     addresses, so warp 0's miss fills L1 and the other 7 warps hit L1
//     (per-SM): near-zero extra DRAM/L2 traffic, ~2 iterations on this
//     data, correct for any input.
//   - No __syncthreads, no shared memory: each warp is an independent
//     {scan -> 2x LDG.128 -> popc -> 2x STG.128} stream, removing the
//     BAR wait and warp-0 serialization from the critical path while
//     keeping the low front-batched-MLP profile that wins steady-state.
__global__ __launch_bounds__(256)
void fused_rank_kernel(const float4* __restrict__ x, float4* __restrict__ out)
{
    const int b = blockIdx.x >> 7;                 // 128 blocks per batch
    const size_t base = (size_t)b * BATCH_VEC4;
    const int lane = threadIdx.x & 31;

    // Per-warp presence scan over the shared prefix (same addresses for
    // all warps in the block -> L1 broadcast).
    const float4* __restrict__ p = x + base;
    unsigned int m = 0;
    for (int i = lane; i < TRAIN_VEC4; i += 32) {
        float4 v = __ldg(&p[i]);
        m |= 1u << (int)v.x;
        m |= 1u << (int)v.y;
        m |= 1u << (int)v.z;
        m |= 1u << (int)v.w;
        // warp-union early exit (safe: OR is monotone)
        if (__reduce_or_sync(0xffffffffu, m) == FULL_MASK) { m = FULL_MASK; break; }
    }
    const unsigned int mask = __reduce_or_sync(0xffffffffu, m);

    // Rank phase: 512 float4 per block, 2 per thread.
    const size_t i0 = base + ((size_t)(blockIdx.x & 127) << 9) + threadIdx.x;
    const size_t i1 = i0 + 256;

    float4 v0 = __ldcs(&x[i0]);
    float4 v1 = __ldcs(&x[i1]);

    float4 r0, r1;
    r0.x = (float)__popc(mask & ((1u << (int)v0.x) - 1u));
    r0.y = (float)__popc(mask & ((1u << (int)v0.y) - 1u));
    r0.z = (float)__popc(mask & ((1u << (int)v0.z) - 1u));
    r0.w = (float)__popc(mask & ((1u << (int)v0.w) - 1u));
    r1.x = (float)__popc(mask & ((1u << (int)v1.x) - 1u));
    r1.y = (float)__popc(mask & ((1u << (int)v1.y) - 1u));
    r1.z = (float)__popc(mask & ((1u << (int)v1.z) - 1u));
    r1.w = (float)__popc(mask & ((1u << (int)v1.w) - 1u));

    __stcs(&out[i0], r0);
    __stcs(&out[i1], r1);
}

extern "C" void kernel_launch(void* const* d_in, const int* in_sizes, int n_in,
                              void* d_out, int out_size)
{
    const float4* x  = (const float4*)d_in[0];   // [B, S, F] float32
    float4* out      = (float4*)d_out;           // [B, S, F] float32

    const int blocks = BATCH * 128;              // 16384
    fused_rank_kernel<<<blocks, 256>>>(x, out);
}